// round 2
// baseline (speedup 1.0000x reference)
#include <cuda_runtime.h>
#include <cstdint>

// VectorQuantizer: latents [B=8, D=512, T=2048] f32, embedding [K=8192, D=512] f32
// out [B, D, T] f32 = embedding[argmin_k dist2][d] transposed back.
//
// Numerics contract (must match jax-CPU fp32 reference bitwise on the argmin):
//   X    = x_sq per token : strictly sequential fp32  add(mul(v,v)), d ascending
//   C_k  = dot(x, e_k)    : strictly sequential fp32  FMA, d ascending
//   s_k  = fl(fl(X - fl(2*C_k)) + Q_k)   (explicit round-to-nearest ops, no contraction)
//   argmin: first occurrence (lowest index) on ties.

#define BB 8
#define DD 512
#define TT 2048
#define KK 8192
#define MM (BB * TT)          // 16384 tokens

#define TM 64                 // tokens per CTA
#define TN 128                // codes per tile
#define KC 32                 // d-chunk
#define NTHREADS 256
#define ESTRIDE 132           // padded es row stride (floats)
#define ESBUF (KC * ESTRIDE)  // 4224 floats per buffer

// dynamic smem layout (floats):
//   xs   [512][64]        32768
//   es   [2][KC][ESTRIDE]  8448
//   rv   [64][16]          1024
//   ri   [64][16]          1024  (ints)
//   widx [64]                64  (ints)
#define SMEM_FLOATS (32768 + 2 * ESBUF + 1024 + 1024 + 64)
#define SMEM_BYTES (SMEM_FLOATS * 4)

__device__ float g_X[MM];
__device__ float g_Q[KK];

__global__ void vq_precompute(const float* __restrict__ lat,
                              const float* __restrict__ emb) {
    int i = blockIdx.x * blockDim.x + threadIdx.x;
    if (i < MM) {
        int b = i >> 11;
        int t = i & (TT - 1);
        const float* p = lat + (size_t)b * DD * TT + t;
        float s = 0.0f;
        #pragma unroll 8
        for (int d = 0; d < DD; d++) {
            float v = p[(size_t)d * TT];
            s = __fadd_rn(s, __fmul_rn(v, v));   // strict sequential, no FMA
        }
        g_X[i] = s;
    } else if (i < MM + KK) {
        int k = i - MM;
        const float* p = emb + (size_t)k * DD;
        float s = 0.0f;
        #pragma unroll 8
        for (int d = 0; d < DD; d++) {
            float v = p[d];
            s = __fadd_rn(s, __fmul_rn(v, v));
        }
        g_Q[k] = s;
    }
}

__global__ void __launch_bounds__(NTHREADS, 1)
vq_main(const float* __restrict__ lat,
        const float* __restrict__ emb,
        float* __restrict__ out) {
    extern __shared__ float sm[];
    float* xs = sm;                         // [512][64]
    float* es = sm + 32768;                 // [2][KC][ESTRIDE]
    float* rv = es + 2 * ESBUF;             // [64][16]
    int*   ri = (int*)(rv + 1024);          // [64][16]
    int* widx = ri + 1024;                  // [64]

    const int tid = threadIdx.x;
    const int tx = tid & 15;                // code group (8 codes)
    const int ty = tid >> 4;                // token group (4 tokens)

    const int m0 = blockIdx.x * TM;         // first token of this tile
    const int b  = m0 >> 11;
    const int t0 = m0 & (TT - 1);
    const float* latb = lat + (size_t)b * DD * TT;

    // ---- stage x tile: xs[d][t], coalesced float4 ----
    for (int i = tid; i < 512 * 16; i += NTHREADS) {
        int d  = i >> 4;
        int tw = (i & 15) * 4;
        float4 v = *(const float4*)(latb + (size_t)d * TT + t0 + tw);
        *(float4*)(xs + d * 64 + tw) = v;
    }
    __syncthreads();

    float Xv[4];
    float bestv[4];
    int   besti[4];
    #pragma unroll
    for (int i = 0; i < 4; i++) {
        Xv[i] = g_X[m0 + 4 * ty + i];
        bestv[i] = 3.4e38f;
        besti[i] = 0;
    }

    float4 pf[4];

    for (int ct = 0; ct < KK / TN; ct++) {         // 64 code tiles
        const int c0 = ct << 7;
        float acc[4][8];
        #pragma unroll
        for (int i = 0; i < 4; i++)
            #pragma unroll
            for (int j = 0; j < 8; j++) acc[i][j] = 0.0f;

        // preload chunk 0
        #pragma unroll
        for (int j = 0; j < 4; j++) {
            int q = tid + NTHREADS * j;            // 1024 float4 per chunk
            int c = q >> 3;
            int k4 = q & 7;
            pf[j] = *(const float4*)(emb + (size_t)(c0 + c) * DD + k4 * 4);
        }
        #pragma unroll
        for (int j = 0; j < 4; j++) {
            int q = tid + NTHREADS * j;
            int c = q >> 3;
            int kk = (q & 7) * 4;
            es[(kk + 0) * ESTRIDE + c] = pf[j].x;
            es[(kk + 1) * ESTRIDE + c] = pf[j].y;
            es[(kk + 2) * ESTRIDE + c] = pf[j].z;
            es[(kk + 3) * ESTRIDE + c] = pf[j].w;
        }
        __syncthreads();

        for (int cc = 0; cc < DD / KC; cc++) {     // 16 d-chunks
            if (cc < 15) {
                #pragma unroll
                for (int j = 0; j < 4; j++) {
                    int q = tid + NTHREADS * j;
                    int c = q >> 3;
                    int k4 = q & 7;
                    pf[j] = *(const float4*)(emb + (size_t)(c0 + c) * DD
                                             + (cc + 1) * KC + k4 * 4);
                }
            }
            const float* eb = es + (cc & 1) * ESBUF;
            const int dbase = cc * KC;
            #pragma unroll 8
            for (int kk = 0; kk < KC; kk++) {
                const float4 xv = *(const float4*)(xs + (dbase + kk) * 64 + 4 * ty);
                const float4 e0 = *(const float4*)(eb + kk * ESTRIDE + 8 * tx);
                const float4 e1 = *(const float4*)(eb + kk * ESTRIDE + 8 * tx + 4);
                const float xr[4] = {xv.x, xv.y, xv.z, xv.w};
                const float er[8] = {e0.x, e0.y, e0.z, e0.w,
                                     e1.x, e1.y, e1.z, e1.w};
                #pragma unroll
                for (int i = 0; i < 4; i++)
                    #pragma unroll
                    for (int j = 0; j < 8; j++)
                        acc[i][j] = __fmaf_rn(xr[i], er[j], acc[i][j]);
            }
            __syncthreads();
            if (cc < 15) {
                float* ebn = es + ((cc + 1) & 1) * ESBUF;
                #pragma unroll
                for (int j = 0; j < 4; j++) {
                    int q = tid + NTHREADS * j;
                    int c = q >> 3;
                    int kk = (q & 7) * 4;
                    ebn[(kk + 0) * ESTRIDE + c] = pf[j].x;
                    ebn[(kk + 1) * ESTRIDE + c] = pf[j].y;
                    ebn[(kk + 2) * ESTRIDE + c] = pf[j].z;
                    ebn[(kk + 3) * ESTRIDE + c] = pf[j].w;
                }
                __syncthreads();
            }
        }

        // ---- min update: s = fl(fl(X - 2C) + Q), scan ascending code index ----
        #pragma unroll
        for (int j = 0; j < 8; j++) {
            const int code = c0 + 8 * tx + j;
            const float q = __ldg(&g_Q[code]);
            #pragma unroll
            for (int i = 0; i < 4; i++) {
                float s = __fadd_rn(__fsub_rn(Xv[i],
                                    __fmul_rn(2.0f, acc[i][j])), q);
                if (s < bestv[i]) { bestv[i] = s; besti[i] = code; }
            }
        }
    }

    // ---- cross-thread (val, idx) reduce, lowest-index tie break ----
    __syncthreads();
    #pragma unroll
    for (int i = 0; i < 4; i++) {
        rv[(4 * ty + i) * 16 + tx] = bestv[i];
        ri[(4 * ty + i) * 16 + tx] = besti[i];
    }
    __syncthreads();
    if (tid < TM) {
        float bv = rv[tid * 16];
        int   bi = ri[tid * 16];
        #pragma unroll
        for (int x = 1; x < 16; x++) {
            float v = rv[tid * 16 + x];
            int   id = ri[tid * 16 + x];
            if (v < bv || (v == bv && id < bi)) { bv = v; bi = id; }
        }
        widx[tid] = bi;
    }
    __syncthreads();

    // ---- gather + transpose epilogue: out[b, d, t0+tt] = emb[idx[tt]][d] ----
    for (int i = tid; i < DD * TM; i += NTHREADS) {
        int d  = i >> 6;
        int tt = i & 63;
        out[(size_t)b * DD * TT + (size_t)d * TT + t0 + tt] =
            __ldg(&emb[(size_t)widx[tt] * DD + d]);
    }
}

extern "C" void kernel_launch(void* const* d_in, const int* in_sizes, int n_in,
                              void* d_out, int out_size) {
    const float* lat = (const float*)d_in[0];   // latents  [8, 512, 2048]
    const float* emb = (const float*)d_in[1];   // embedding [8192, 512]
    float* out = (float*)d_out;                 // [8, 512, 2048]

    cudaFuncSetAttribute(vq_main, cudaFuncAttributeMaxDynamicSharedMemorySize,
                         SMEM_BYTES);

    vq_precompute<<<(MM + KK + NTHREADS - 1) / NTHREADS, NTHREADS>>>(lat, emb);
    vq_main<<<MM / TM, NTHREADS, SMEM_BYTES>>>(lat, emb, out);
}

// round 5
// speedup vs baseline: 1.0706x; 1.0706x over previous
#include <cuda_runtime.h>
#include <cstdint>

// VectorQuantizer: latents [B=8, D=512, T=2048] f32, embedding [K=8192, D=512] f32
// out [B, D, T] f32 = embedding[argmin_k dist2][d] transposed back.
//
// Numerics contract (bit-exact vs jax-CPU fp32 reference, verified rel_err=0.0 in R1):
//   X    = x_sq per token : strictly sequential fp32  add(mul(v,v)), d ascending
//   C_k  = dot(x, e_k)    : strictly sequential fp32  FMA, d ascending
//          (fma.rn.f32x2 halves are per-lane rn FMA -> chain unchanged)
//   s_k  = fl(fl(X - fl(2*C_k)) + Q_k)   explicit rn ops, no contraction
//   argmin: first occurrence (lowest index) on ties.

#define BB 8
#define DD 512
#define TT 2048
#define KK 8192
#define MM (BB * TT)          // 16384 tokens

#define TM 128                // tokens per CTA  -> grid = 128 (single wave)
#define TN 128                // codes per tile
#define KC 32                 // d-chunk
#define NTHREADS 512
#define ESTRIDE 132           // padded es row stride (floats)
#define ESBUF (KC * ESTRIDE)  // 4224 floats per buffer
#define XSBUF (KC * TM)       // 4096 floats per buffer

// dynamic smem (floats):
//   xs [2][KC][TM]      8192
//   es [2][KC][ESTRIDE] 8448
//   rv [128][8]         1024
//   ri [128][8]         1024 (ints)
//   widx[128]            128 (ints)
#define SMEM_FLOATS (2 * XSBUF + 2 * ESBUF + 1024 + 1024 + 128)
#define SMEM_BYTES (SMEM_FLOATS * 4)

__device__ float g_X[MM];
__device__ float g_Q[KK];

// ---- packed f32x2 helpers (PTX-only; bit-exact per half) ----
__device__ __forceinline__ unsigned long long dupf(float v) {
    unsigned long long r;
    asm("mov.b64 %0, {%1, %1};" : "=l"(r) : "f"(v));
    return r;
}
__device__ __forceinline__ void fma2(unsigned long long& a,
                                     unsigned long long x,
                                     unsigned long long e) {
    asm("fma.rn.f32x2 %0, %1, %2, %0;" : "+l"(a) : "l"(x), "l"(e));
}
__device__ __forceinline__ float2 unpk(unsigned long long a) {
    float2 f;
    asm("mov.b64 {%0, %1}, %2;" : "=f"(f.x), "=f"(f.y) : "l"(a));
    return f;
}

__global__ void vq_precompute(const float* __restrict__ lat,
                              const float* __restrict__ emb) {
    int i = blockIdx.x * blockDim.x + threadIdx.x;
    if (i < MM) {
        int b = i >> 11;
        int t = i & (TT - 1);
        const float* p = lat + (size_t)b * DD * TT + t;
        float s = 0.0f;
        #pragma unroll 8
        for (int d = 0; d < DD; d++) {
            float v = p[(size_t)d * TT];
            s = __fadd_rn(s, __fmul_rn(v, v));   // strict sequential, no FMA
        }
        g_X[i] = s;
    } else if (i < MM + KK) {
        int k = i - MM;
        const float* p = emb + (size_t)k * DD;
        float s = 0.0f;
        #pragma unroll 8
        for (int d = 0; d < DD; d++) {
            float v = p[d];
            s = __fadd_rn(s, __fmul_rn(v, v));
        }
        g_Q[k] = s;
    }
}

__global__ void __launch_bounds__(NTHREADS, 1)
vq_main(const float* __restrict__ lat,
        const float* __restrict__ emb,
        float* __restrict__ out) {
    extern __shared__ float sm[];
    float* xs = sm;                         // [2][KC][TM]
    float* es = sm + 2 * XSBUF;             // [2][KC][ESTRIDE]
    float* rv = es + 2 * ESBUF;             // [128][8]
    int*   ri = (int*)(rv + 1024);          // [128][8]
    int* widx = ri + 1024;                  // [128]

    const int tid = threadIdx.x;
    const int tx = tid & 7;                 // code group: 4 interleaved float4s
    const int ty = tid >> 3;                // 0..63 -> tokens 2*ty, 2*ty+1

    const int m0 = blockIdx.x * TM;
    const int b  = m0 >> 11;
    const int t0 = m0 & (TT - 1);
    const float* latb = lat + (size_t)b * DD * TT;

    float Xv[2];
    float bestv[2];
    int   besti[2];
    #pragma unroll
    for (int i = 0; i < 2; i++) {
        Xv[i] = g_X[m0 + 2 * ty + i];
        bestv[i] = 3.4e38f;
        besti[i] = 0;
    }

    float4 pe[2], px[2];

    for (int ct = 0; ct < KK / TN; ct++) {          // 64 code tiles
        const int c0 = ct << 7;
        unsigned long long acc[2][8];               // [token][2*g+pp]
        #pragma unroll
        for (int i = 0; i < 2; i++)
            #pragma unroll
            for (int j = 0; j < 8; j++) acc[i][j] = 0ULL;

        // ---- preload + stage chunk 0 ----
        #pragma unroll
        for (int j = 0; j < 2; j++) {
            int q  = tid + NTHREADS * j;            // e: 1024 float4 per chunk
            int c  = q >> 3;
            int k4 = q & 7;
            pe[j] = *(const float4*)(emb + (size_t)(c0 + c) * DD + k4 * 4);
            int d  = q >> 5;                        // x: 1024 float4 per chunk
            int tw = (q & 31) * 4;
            px[j] = *(const float4*)(latb + (size_t)d * TT + t0 + tw);
        }
        #pragma unroll
        for (int j = 0; j < 2; j++) {
            int q  = tid + NTHREADS * j;
            int c  = q >> 3;
            int kk = (q & 7) * 4;
            es[(kk + 0) * ESTRIDE + c] = pe[j].x;
            es[(kk + 1) * ESTRIDE + c] = pe[j].y;
            es[(kk + 2) * ESTRIDE + c] = pe[j].z;
            es[(kk + 3) * ESTRIDE + c] = pe[j].w;
            int d  = q >> 5;
            int tw = (q & 31) * 4;
            *(float4*)(xs + d * TM + tw) = px[j];
        }
        __syncthreads();

        for (int cc = 0; cc < DD / KC; cc++) {      // 16 d-chunks
            if (cc < 15) {
                #pragma unroll
                for (int j = 0; j < 2; j++) {
                    int q  = tid + NTHREADS * j;
                    int c  = q >> 3;
                    int k4 = q & 7;
                    pe[j] = *(const float4*)(emb + (size_t)(c0 + c) * DD
                                             + (cc + 1) * KC + k4 * 4);
                    int d  = q >> 5;
                    int tw = (q & 31) * 4;
                    px[j] = *(const float4*)(latb
                             + (size_t)((cc + 1) * KC + d) * TT + t0 + tw);
                }
            }
            const float* eb = es + (cc & 1) * ESBUF;
            const float* xb = xs + (cc & 1) * XSBUF;

            #pragma unroll 8
            for (int kk = 0; kk < KC; kk++) {
                const float2 xv = *(const float2*)(xb + kk * TM + 2 * ty);
                const unsigned long long xd0 = dupf(xv.x);
                const unsigned long long xd1 = dupf(xv.y);
                #pragma unroll
                for (int g = 0; g < 4; g++) {
                    // codes c0 + 4*tx + 32*g + {0..3}; conflict-free LDS.128
                    const ulonglong2 e2 = *(const ulonglong2*)
                        (eb + kk * ESTRIDE + 4 * tx + 32 * g);
                    fma2(acc[0][2 * g],     xd0, e2.x);
                    fma2(acc[0][2 * g + 1], xd0, e2.y);
                    fma2(acc[1][2 * g],     xd1, e2.x);
                    fma2(acc[1][2 * g + 1], xd1, e2.y);
                }
            }
            __syncthreads();
            if (cc < 15) {
                float* ebn = es + ((cc + 1) & 1) * ESBUF;
                float* xbn = xs + ((cc + 1) & 1) * XSBUF;
                #pragma unroll
                for (int j = 0; j < 2; j++) {
                    int q  = tid + NTHREADS * j;
                    int c  = q >> 3;
                    int kk = (q & 7) * 4;
                    ebn[(kk + 0) * ESTRIDE + c] = pe[j].x;
                    ebn[(kk + 1) * ESTRIDE + c] = pe[j].y;
                    ebn[(kk + 2) * ESTRIDE + c] = pe[j].z;
                    ebn[(kk + 3) * ESTRIDE + c] = pe[j].w;
                    int d  = q >> 5;
                    int tw = (q & 31) * 4;
                    *(float4*)(xbn + d * TM + tw) = px[j];
                }
                __syncthreads();
            }
        }

        // ---- min update: s = fl(fl(X - 2C) + Q); in-thread codes ascend ----
        #pragma unroll
        for (int g = 0; g < 4; g++) {
            #pragma unroll
            for (int pp = 0; pp < 2; pp++) {
                const int cbase = c0 + 4 * tx + 32 * g + 2 * pp;
                const float q0 = __ldg(&g_Q[cbase]);
                const float q1 = __ldg(&g_Q[cbase + 1]);
                #pragma unroll
                for (int i = 0; i < 2; i++) {
                    const float2 c2 = unpk(acc[i][2 * g + pp]);
                    float s0 = __fadd_rn(__fsub_rn(Xv[i],
                                   __fmul_rn(2.0f, c2.x)), q0);
                    float s1 = __fadd_rn(__fsub_rn(Xv[i],
                                   __fmul_rn(2.0f, c2.y)), q1);
                    if (s0 < bestv[i]) { bestv[i] = s0; besti[i] = cbase; }
                    if (s1 < bestv[i]) { bestv[i] = s1; besti[i] = cbase + 1; }
                }
            }
        }
    }

    // ---- cross-thread (val, idx) reduce, lowest-index tie break ----
    __syncthreads();
    #pragma unroll
    for (int i = 0; i < 2; i++) {
        rv[(2 * ty + i) * 8 + tx] = bestv[i];
        ri[(2 * ty + i) * 8 + tx] = besti[i];
    }
    __syncthreads();
    if (tid < TM) {
        float bv = rv[tid * 8];
        int   bi = ri[tid * 8];
        #pragma unroll
        for (int x = 1; x < 8; x++) {
            float v  = rv[tid * 8 + x];
            int   id = ri[tid * 8 + x];
            if (v < bv || (v == bv && id < bi)) { bv = v; bi = id; }
        }
        widx[tid] = bi;
    }
    __syncthreads();

    // ---- gather + transpose epilogue: out[b, d, t0+tt] = emb[idx[tt]][d] ----
    for (int i = tid; i < DD * TM; i += NTHREADS) {
        int d  = i >> 7;
        int tt = i & 127;
        out[(size_t)b * DD * TT + (size_t)d * TT + t0 + tt] =
            __ldg(&emb[(size_t)widx[tt] * DD + d]);
    }
}

extern "C" void kernel_launch(void* const* d_in, const int* in_sizes, int n_in,
                              void* d_out, int out_size) {
    const float* lat = (const float*)d_in[0];   // latents   [8, 512, 2048]
    const float* emb = (const float*)d_in[1];   // embedding [8192, 512]
    float* out = (float*)d_out;                 // [8, 512, 2048]

    cudaFuncSetAttribute(vq_main, cudaFuncAttributeMaxDynamicSharedMemorySize,
                         SMEM_BYTES);

    vq_precompute<<<(MM + KK + NTHREADS - 1) / NTHREADS, NTHREADS>>>(lat, emb);
    vq_main<<<MM / TM, NTHREADS, SMEM_BYTES>>>(lat, emb, out);
}